// round 16
// baseline (speedup 1.0000x reference)
#include <cuda_runtime.h>
#include <cuda_bf16.h>
#include <cstdint>

#define B_   32
#define T_   64
#define E_   512
#define H_   1024
#define V_   32000
#define G3_  3072
#define SOS_ 1
#define SPG  6        // gates split-K
#define NJG  (24*SPG) // 144
#define VT_  250      // vocab tiles of 128
#define KT_  64       // logits K tiles of 16

// gate weight fragment offsets (uint4 units): [jt*8+mt][ktile][lane]
#define OFF_WIH0 0            // KT=32: 24*8*32*32 = 196608
#define OFF_WHH0 196608       // KT=64: 393216
#define OFF_WIH1 589824
#define OFF_WHH1 983040
#define GWF_TOT  1376256

// ---------------- persistent device state ----------------
__device__ float g_h0T[2][H_*B_];            // fp32 hidden, transposed [k][b], ping-pong
__device__ float g_h1T[2][H_*B_];
__device__ float g_giP0[SPG][G3_*B_];        // split-K partials, layout [j][b]
__device__ float g_ghP0[SPG][G3_*B_];
__device__ float g_giP1[SPG][G3_*B_];
__device__ float g_ghP1[SPG][G3_*B_];
__device__ unsigned long long g_argmax[B_];  // packed (orderable_val<<32 | ~index)

// logits w_out bf16 hi/lo A-fragments: ((vt*8+mt)*KT_+kt)*32+lane -> uint4
__device__ uint4 g_wfHi[(size_t)VT_*8*KT_*32];
__device__ uint4 g_wfLo[(size_t)VT_*8*KT_*32];
// gate weight A-fragments
__device__ uint4 g_gwfHi[GWF_TOT];
__device__ uint4 g_gwfLo[GWF_TOT];
// B-fragments (activations) hi/lo: 1/2=h0 parity0/1, 3/4=h1 parity0/1
__device__ uint2 g_bfHi[5][64*4*32];
__device__ uint2 g_bfLo[5][64*4*32];

__device__ __forceinline__ float* hbuf(int code){
    switch(code){
        case 0:  return g_h0T[0];
        case 1:  return g_h0T[1];
        case 2:  return g_h1T[0];
        default: return g_h1T[1];
    }
}

__device__ __forceinline__ unsigned long long packv(float f, unsigned v){
    unsigned u = __float_as_uint(f);
    u = (u & 0x80000000u) ? ~u : (u | 0x80000000u);   // monotonic order-preserving map
    return ((unsigned long long)u << 32) | (unsigned long long)(0xFFFFFFFFu - v);
}

// baseline-sm_103 HMMA: m16n8k16 bf16 -> f32, accumulate in place
__device__ __forceinline__ void mma16816(float* d, const uint32_t* a, const uint32_t* b){
    asm volatile("mma.sync.aligned.m16n8k16.row.col.f32.bf16.bf16.f32 "
        "{%0,%1,%2,%3}, {%4,%5,%6,%7}, {%8,%9}, {%0,%1,%2,%3};"
        : "+f"(d[0]), "+f"(d[1]), "+f"(d[2]), "+f"(d[3])
        : "r"(a[0]), "r"(a[1]), "r"(a[2]), "r"(a[3]), "r"(b[0]), "r"(b[1]));
}

__device__ __forceinline__ void write_bfrag(int code, int k, int b, float hv){
    __nv_bfloat16 hi = __float2bfloat16(hv);
    __nv_bfloat16 lo = __float2bfloat16(hv - __bfloat162float(hi));
    int ktile = k >> 4, kin = k & 15;
    int reg = kin >> 3, c = kin & 7;
    int lane = (b & 7)*4 + (c >> 1);
    int ntile = b >> 3;
    int half = c & 1;
    size_t off = ((size_t)(ktile*4 + ntile)*32 + lane)*4 + reg*2 + half; // ushort units
    ((unsigned short*)g_bfHi[code])[off] = __bfloat16_as_ushort(hi);
    ((unsigned short*)g_bfLo[code])[off] = __bfloat16_as_ushort(lo);
}

// pack two floats to bf16x2 hi and lo words
__device__ __forceinline__ void split2(float x0, float x1, uint32_t& hw, uint32_t& lw){
    __nv_bfloat16 h0 = __float2bfloat16(x0), h1 = __float2bfloat16(x1);
    __nv_bfloat16 l0 = __float2bfloat16(x0 - __bfloat162float(h0));
    __nv_bfloat16 l1 = __float2bfloat16(x1 - __bfloat162float(h1));
    hw = (uint32_t)__bfloat16_as_ushort(h0) | ((uint32_t)__bfloat16_as_ushort(h1) << 16);
    lw = (uint32_t)__bfloat16_as_ushort(l0) | ((uint32_t)__bfloat16_as_ushort(l1) << 16);
}

// =============================================================================
// Fused step-head kernel: gi0 (emb gather), gh0, gh1 — all independent given
// state(t-1) and argmax(t-1).  grid = 3*NJG = 432 blocks, 256 thr.
// =============================================================================
__global__ __launch_bounds__(256) void k_gatesA(const float* __restrict__ emb, int t, int p)
{
    __shared__ int tok_s[B_];
    const int tid = threadIdx.x, wid = tid >> 5, lane = tid & 31;
    const int sect = blockIdx.x / NJG;          // 0=gi0, 1=gh0, 2=gh1
    const int rem  = blockIdx.x % NJG;
    const int s = rem / 24, jt = rem % 24;

    const int KT = (sect == 0) ? 32 : 64;
    const int matOff = (sect == 0) ? OFF_WIH0 : (sect == 1) ? OFF_WHH0 : OFF_WHH1;
    float* __restrict__ out = (sect == 0) ? g_giP0[s] : (sect == 1) ? g_ghP0[s] : g_ghP1[s];

    const int kt0 = (KT * s) / SPG;
    const int kt1 = (KT * (s+1)) / SPG;

    const uint4* __restrict__ aHi = g_gwfHi + matOff + ((size_t)(jt*8 + wid)*KT)*32 + lane;
    const uint4* __restrict__ aLo = g_gwfLo + matOff + ((size_t)(jt*8 + wid)*KT)*32 + lane;

    float acc[4][4];
    #pragma unroll
    for (int n=0;n<4;n++){ acc[n][0]=0.f; acc[n][1]=0.f; acc[n][2]=0.f; acc[n][3]=0.f; }

    if (sect == 0){
        // ---- gi0: B = emb[tok] gathered per lane ----
        if (tid < B_){
            int tk = SOS_;
            if (t > 0) tk = (int)(0xFFFFFFFFu - (unsigned)(g_argmax[tid] & 0xFFFFFFFFull));
            tok_s[tid] = tk;
        }
        __syncthreads();
        const int n_in = lane >> 2;
        const int kc   = (lane & 3)*2;
        const float* __restrict__ row[4];
        #pragma unroll
        for (int nt=0; nt<4; nt++) row[nt] = emb + (size_t)tok_s[nt*8 + n_in]*E_;

        uint4 ah = aHi[(size_t)kt0*32], al = aLo[(size_t)kt0*32];
        for (int kt = kt0; kt < kt1; kt++){
            uint4 ah_n, al_n;
            if (kt+1 < kt1){ ah_n = aHi[(size_t)(kt+1)*32]; al_n = aLo[(size_t)(kt+1)*32]; }
            const int k0 = kt*16 + kc;
            #pragma unroll
            for (int nt=0; nt<4; nt++){
                float2 x0 = *(const float2*)(row[nt] + k0);
                float2 x1 = *(const float2*)(row[nt] + k0 + 8);
                uint2 bh, bl;
                split2(x0.x, x0.y, bh.x, bl.x);
                split2(x1.x, x1.y, bh.y, bl.y);
                mma16816(acc[nt], (const uint32_t*)&ah, (const uint32_t*)&bh);
                mma16816(acc[nt], (const uint32_t*)&ah, (const uint32_t*)&bl);
                mma16816(acc[nt], (const uint32_t*)&al, (const uint32_t*)&bh);
            }
            ah = ah_n; al = al_n;
        }
    } else {
        // ---- gh: B = h fragments (layer 0 -> code 1+p, layer 1 -> code 3+p) ----
        const int bcode = (sect == 1) ? (1+p) : (3+p);
        const uint2* __restrict__ bHi = g_bfHi[bcode];
        const uint2* __restrict__ bLo = g_bfLo[bcode];

        uint4 ah = aHi[(size_t)kt0*32], al = aLo[(size_t)kt0*32];
        for (int kt = kt0; kt < kt1; kt++){
            uint4 ah_n, al_n;
            if (kt+1 < kt1){ ah_n = aHi[(size_t)(kt+1)*32]; al_n = aLo[(size_t)(kt+1)*32]; }
            uint2 bh[4], bl[4];
            #pragma unroll
            for (int nt=0; nt<4; nt++){
                bh[nt] = bHi[(kt*4 + nt)*32 + lane];
                bl[nt] = bLo[(kt*4 + nt)*32 + lane];
            }
            #pragma unroll
            for (int nt=0; nt<4; nt++){
                mma16816(acc[nt], (const uint32_t*)&ah, (const uint32_t*)&bh[nt]);
                mma16816(acc[nt], (const uint32_t*)&ah, (const uint32_t*)&bl[nt]);
                mma16816(acc[nt], (const uint32_t*)&al, (const uint32_t*)&bh[nt]);
            }
            ah = ah_n; al = al_n;
        }
    }

    const int g  = lane >> 2, c0 = (lane & 3)*2;
    const int j0 = jt*128 + wid*16 + g;
    #pragma unroll
    for (int nt=0; nt<4; nt++){
        const int b = nt*8 + c0;
        out[(size_t)j0     *B_ + b    ] = acc[nt][0];
        out[(size_t)j0     *B_ + b + 1] = acc[nt][1];
        out[(size_t)(j0+8) *B_ + b    ] = acc[nt][2];
        out[(size_t)(j0+8) *B_ + b + 1] = acc[nt][3];
    }
}

// =============================================================================
// Layer-1 input gates: giP1 = h0_new @ wih1^T.  grid = NJG.
// =============================================================================
__global__ __launch_bounds__(256) void k_gates_gi1(int bcode)
{
    const int tid = threadIdx.x, wid = tid >> 5, lane = tid & 31;
    const int s = blockIdx.x / 24, jt = blockIdx.x % 24;
    const int KT = 64;

    const uint2* __restrict__ bHi = g_bfHi[bcode];
    const uint2* __restrict__ bLo = g_bfLo[bcode];
    const int kt0 = (KT * s) / SPG;
    const int kt1 = (KT * (s+1)) / SPG;

    const uint4* __restrict__ aHi = g_gwfHi + OFF_WIH1 + ((size_t)(jt*8 + wid)*KT)*32 + lane;
    const uint4* __restrict__ aLo = g_gwfLo + OFF_WIH1 + ((size_t)(jt*8 + wid)*KT)*32 + lane;

    float acc[4][4];
    #pragma unroll
    for (int n=0;n<4;n++){ acc[n][0]=0.f; acc[n][1]=0.f; acc[n][2]=0.f; acc[n][3]=0.f; }

    uint4 ah = aHi[(size_t)kt0*32], al = aLo[(size_t)kt0*32];
    for (int kt = kt0; kt < kt1; kt++){
        uint4 ah_n, al_n;
        if (kt+1 < kt1){ ah_n = aHi[(size_t)(kt+1)*32]; al_n = aLo[(size_t)(kt+1)*32]; }
        uint2 bh[4], bl[4];
        #pragma unroll
        for (int nt=0; nt<4; nt++){
            bh[nt] = bHi[(kt*4 + nt)*32 + lane];
            bl[nt] = bLo[(kt*4 + nt)*32 + lane];
        }
        #pragma unroll
        for (int nt=0; nt<4; nt++){
            mma16816(acc[nt], (const uint32_t*)&ah, (const uint32_t*)&bh[nt]);
            mma16816(acc[nt], (const uint32_t*)&ah, (const uint32_t*)&bl[nt]);
            mma16816(acc[nt], (const uint32_t*)&al, (const uint32_t*)&bh[nt]);
        }
        ah = ah_n; al = al_n;
    }

    const int g  = lane >> 2, c0 = (lane & 3)*2;
    const int j0 = jt*128 + wid*16 + g;
    float* __restrict__ out = g_giP1[s];
    #pragma unroll
    for (int nt=0; nt<4; nt++){
        const int b = nt*8 + c0;
        out[(size_t)j0     *B_ + b    ] = acc[nt][0];
        out[(size_t)j0     *B_ + b + 1] = acc[nt][1];
        out[(size_t)(j0+8) *B_ + b    ] = acc[nt][2];
        out[(size_t)(j0+8) *B_ + b + 1] = acc[nt][3];
    }
}

// =============================================================================
// GRU combine: sums split-K partials, writes fp32 h + bf16 hi/lo B-fragments
// =============================================================================
__global__ __launch_bounds__(256) void k_combine(
    const float* __restrict__ bih, const float* __restrict__ bhh,
    int code_old, int code_new, int fragcode, int reset, int layer)
{
    int idx = blockIdx.x*256 + threadIdx.x;   // 0..32767
    int b = idx & 31, k = idx >> 5;
    const float* giP = layer ? (const float*)g_giP1 : (const float*)g_giP0;
    const float* ghP = layer ? (const float*)g_ghP1 : (const float*)g_ghP0;
    float gr=0.f, gz=0.f, gn=0.f, hr=0.f, hz=0.f, hn=0.f;
    #pragma unroll
    for (int s=0;s<SPG;s++){
        const float* gi = giP + (size_t)s*G3_*B_;
        const float* gh = ghP + (size_t)s*G3_*B_;
        gr += gi[(size_t)k*B_ + b];
        gz += gi[(size_t)(H_  +k)*B_ + b];
        gn += gi[(size_t)(2*H_+k)*B_ + b];
        hr += gh[(size_t)k*B_ + b];
        hz += gh[(size_t)(H_  +k)*B_ + b];
        hn += gh[(size_t)(2*H_+k)*B_ + b];
    }
    float r = 1.f/(1.f + expf(-(gr + bih[k]     + hr + bhh[k])));
    float z = 1.f/(1.f + expf(-(gz + bih[H_+k]  + hz + bhh[H_+k])));
    float n = tanhf(gn + bih[2*H_+k] + r*(hn + bhh[2*H_+k]));
    float h = hbuf(code_old)[(size_t)k*B_ + b];
    float hv = (1.f - z)*n + z*h;
    hbuf(code_new)[(size_t)k*B_ + b] = hv;
    write_bfrag(fragcode, k, b, hv);
    if (reset && idx < B_) g_argmax[idx] = 0ULL;
}

// =============================================================================
// w_out -> bf16 hi/lo per-lane A-fragments (once per replay)
// =============================================================================
__global__ __launch_bounds__(256) void k_wsplit(const float* __restrict__ w){
    size_t gid = (size_t)blockIdx.x*256 + threadIdx.x;  // 4,096,000
    int lane  = (int)(gid & 31);
    int ktile = (int)((gid >> 5) & 63);
    int mtile = (int)((gid >> 11) & 7);
    int vt    = (int)(gid >> 14);
    int g  = lane >> 2, c0 = (lane & 3)*2;
    int v0 = vt*128 + mtile*16;
    int k0 = ktile*16;
    uint32_t hi[4], lo[4];
    #pragma unroll
    for (int r=0;r<4;r++){
        int row = v0 + g + (r & 1)*8;
        int col = k0 + c0 + (r >> 1)*8;
        split2(w[(size_t)row*H_ + col], w[(size_t)row*H_ + col + 1], hi[r], lo[r]);
    }
    g_wfHi[gid] = make_uint4(hi[0], hi[1], hi[2], hi[3]);
    g_wfLo[gid] = make_uint4(lo[0], lo[1], lo[2], lo[3]);
}

// gate weight W[G3_][K] -> A-fragments at offset matOff (once per replay)
__global__ __launch_bounds__(256) void k_wsplit_g(const float* __restrict__ w, int K, int matOff){
    size_t gid = (size_t)blockIdx.x*256 + threadIdx.x;
    const int KT = K >> 4;
    int lane  = (int)(gid & 31);
    int ktile = (int)((gid >> 5) % KT);
    int mt    = (int)((gid >> 5) / KT);
    int g  = lane >> 2, c0 = (lane & 3)*2;
    int j0 = mt*16;
    int k0 = ktile*16;
    uint32_t hi[4], lo[4];
    #pragma unroll
    for (int r=0;r<4;r++){
        int row = j0 + g + (r & 1)*8;
        int col = k0 + c0 + (r >> 1)*8;
        split2(w[(size_t)row*K + col], w[(size_t)row*K + col + 1], hi[r], lo[r]);
    }
    g_gwfHi[matOff + gid] = make_uint4(hi[0], hi[1], hi[2], hi[3]);
    g_gwfLo[matOff + gid] = make_uint4(lo[0], lo[1], lo[2], lo[3]);
}

// =============================================================================
// Logits via mma.sync bf16 hi/lo + bias + fused argmax
// =============================================================================
__global__ __launch_bounds__(256,3) void k_logits_mma(
    const float* __restrict__ bout, float* __restrict__ out, int t, int bcode)
{
    __shared__ unsigned long long red[8][32];

    const int tid = threadIdx.x, wid = tid >> 5, lane = tid & 31;
    const int vt  = blockIdx.x;

    float acc[4][4];
    #pragma unroll
    for (int n=0;n<4;n++){ acc[n][0]=0.f; acc[n][1]=0.f; acc[n][2]=0.f; acc[n][3]=0.f; }

    const uint4* __restrict__ aHi = g_wfHi + ((size_t)(vt*8 + wid)*KT_)*32 + lane;
    const uint4* __restrict__ aLo = g_wfLo + ((size_t)(vt*8 + wid)*KT_)*32 + lane;
    const uint2* __restrict__ bHi = g_bfHi[bcode];
    const uint2* __restrict__ bLo = g_bfLo[bcode];

    uint4 ah = aHi[0], al = aLo[0];
    for (int kt = 0; kt < KT_; kt++){
        uint4 ah_n, al_n;
        if (kt < KT_-1){ ah_n = aHi[(kt+1)*32]; al_n = aLo[(kt+1)*32]; }
        uint2 bh[4], bl[4];
        #pragma unroll
        for (int nt=0; nt<4; nt++){
            bh[nt] = bHi[(kt*4 + nt)*32 + lane];
            bl[nt] = bLo[(kt*4 + nt)*32 + lane];
        }
        #pragma unroll
        for (int nt=0; nt<4; nt++){
            mma16816(acc[nt], (const uint32_t*)&ah, (const uint32_t*)&bh[nt]);
            mma16816(acc[nt], (const uint32_t*)&ah, (const uint32_t*)&bl[nt]);
            mma16816(acc[nt], (const uint32_t*)&al, (const uint32_t*)&bh[nt]);
        }
        ah = ah_n; al = al_n;
    }

    const int g  = lane >> 2, c0 = (lane & 3)*2;
    const int v0 = vt*128 + wid*16 + g;
    const float bias0 = bout[v0], bias1 = bout[v0 + 8];

    unsigned long long colmax[8];
    #pragma unroll
    for (int nt=0; nt<4; nt++){
        const int b = nt*8 + c0;
        float v00 = acc[nt][0] + bias0;
        float v01 = acc[nt][1] + bias0;
        float v10 = acc[nt][2] + bias1;
        float v11 = acc[nt][3] + bias1;
        out[((size_t)b    *T_ + t)*V_ + v0    ] = v00;
        out[((size_t)(b+1)*T_ + t)*V_ + v0    ] = v01;
        out[((size_t)b    *T_ + t)*V_ + v0 + 8] = v10;
        out[((size_t)(b+1)*T_ + t)*V_ + v0 + 8] = v11;
        unsigned long long p0 = packv(v00, (unsigned)v0);
        unsigned long long q0 = packv(v10, (unsigned)(v0+8));
        unsigned long long p1 = packv(v01, (unsigned)v0);
        unsigned long long q1 = packv(v11, (unsigned)(v0+8));
        colmax[nt*2]   = p0 > q0 ? p0 : q0;
        colmax[nt*2+1] = p1 > q1 ? p1 : q1;
    }
    #pragma unroll
    for (int q=0;q<8;q++){
        #pragma unroll
        for (int off=4; off<32; off<<=1){
            unsigned long long o = __shfl_xor_sync(0xFFFFFFFFu, colmax[q], off);
            if (o > colmax[q]) colmax[q] = o;
        }
    }
    if (lane < 4){
        #pragma unroll
        for (int nt=0; nt<4; nt++){
            red[wid][nt*8 + lane*2    ] = colmax[nt*2];
            red[wid][nt*8 + lane*2 + 1] = colmax[nt*2+1];
        }
    }
    __syncthreads();
    if (tid < B_){
        unsigned long long m = red[0][tid];
        #pragma unroll
        for (int w=1; w<8; w++) if (red[w][tid] > m) m = red[w][tid];
        atomicMax(&g_argmax[tid], m);
    }
}

// =============================================================================
// init / finalize / log_softmax
// =============================================================================
__global__ void k_init(const float* __restrict__ eh){
    int idx = blockIdx.x*256 + threadIdx.x;           // 0..65535
    int k = idx & (H_-1), b = (idx >> 10) & 31, l = idx >> 15;
    float v = eh[idx];
    (l ? g_h1T[0] : g_h0T[0])[(size_t)k*B_ + b] = v;
    write_bfrag(l ? 3 : 1, k, b, v);                  // parity-0 fragment buffers
}

__global__ void k_final(float* __restrict__ dst){
    int idx = blockIdx.x*256 + threadIdx.x;
    int k = idx & (H_-1), b = (idx >> 10) & 31, l = idx >> 15;
    dst[idx] = (l ? g_h1T[0] : g_h0T[0])[(size_t)k*B_ + b];   // parity 0 after 64 steps
}

__global__ __launch_bounds__(256) void k_lsm(float* __restrict__ out){
    float* p = out + (size_t)blockIdx.x * V_;
    __shared__ float red[256];
    float m = -3.4e38f;
    for (int i = threadIdx.x; i < V_; i += 256) m = fmaxf(m, p[i]);
    red[threadIdx.x] = m; __syncthreads();
    for (int s=128; s; s>>=1){
        if (threadIdx.x < s) red[threadIdx.x] = fmaxf(red[threadIdx.x], red[threadIdx.x+s]);
        __syncthreads();
    }
    m = red[0]; __syncthreads();
    float sum = 0.f;
    for (int i = threadIdx.x; i < V_; i += 256) sum += __expf(p[i] - m);
    red[threadIdx.x] = sum; __syncthreads();
    for (int s=128; s; s>>=1){
        if (threadIdx.x < s) red[threadIdx.x] += red[threadIdx.x+s];
        __syncthreads();
    }
    float lse = m + logf(red[0]);
    for (int i = threadIdx.x; i < V_; i += 256) p[i] -= lse;
}

// =============================================================================
extern "C" void kernel_launch(void* const* d_in, const int* in_sizes, int n_in,
                              void* d_out, int out_size) {
    const float* eh   = (const float*)d_in[1];   // encoder_hidden [2,32,1024]
    const float* emb  = (const float*)d_in[2];   // embedding [V,E]
    const float* wih0 = (const float*)d_in[3];
    const float* whh0 = (const float*)d_in[4];
    const float* bih0 = (const float*)d_in[5];
    const float* bhh0 = (const float*)d_in[6];
    const float* wih1 = (const float*)d_in[7];
    const float* whh1 = (const float*)d_in[8];
    const float* bih1 = (const float*)d_in[9];
    const float* bhh1 = (const float*)d_in[10];
    const float* wout = (const float*)d_in[11];
    const float* bout = (const float*)d_in[12];

    float* out  = (float*)d_out;                 // [B,T,V] log-softmax
    float* hfin = out + (size_t)B_*T_*V_;        // [2,B,H]

    // per-replay weight prep (amortized over 64 steps)
    k_wsplit<<<(VT_*8*KT_*32)/256, 256>>>(wout);
    k_wsplit_g<<<(24*8*(E_/16)*32)/256, 256>>>(wih0, E_, OFF_WIH0);
    k_wsplit_g<<<(24*8*(H_/16)*32)/256, 256>>>(whh0, H_, OFF_WHH0);
    k_wsplit_g<<<(24*8*(H_/16)*32)/256, 256>>>(wih1, H_, OFF_WIH1);
    k_wsplit_g<<<(24*8*(H_/16)*32)/256, 256>>>(whh1, H_, OFF_WHH1);

    k_init<<<256,256>>>(eh);
    for (int t=0; t<T_; t++){
        const int p = t & 1;
        // fused: gi0 (emb gather from argmax(t-1)) + gh0 + gh1
        k_gatesA<<<3*NJG, 256>>>(emb, t, p);
        k_combine<<<H_*B_/256,256>>>(bih0, bhh0, p, 1-p, 1+(1-p), 0, 0);
        k_gates_gi1<<<NJG, 256>>>(1+(1-p));
        k_combine<<<H_*B_/256,256>>>(bih1, bhh1, 2+p, 3-p, 3+(1-p), 1, 1);  // + argmax reset
        k_logits_mma<<<VT_,256>>>(bout, out, t, 3+(1-p));
    }
    k_final<<<256,256>>>(hfin);
    k_lsm<<<B_*T_,256>>>(out);
}

// round 17
// speedup vs baseline: 1.0597x; 1.0597x over previous
#include <cuda_runtime.h>
#include <cuda_bf16.h>
#include <cstdint>

#define B_   32
#define T_   64
#define E_   512
#define H_   1024
#define V_   32000
#define G3_  3072
#define SOS_ 1
#define SPG  6        // gates split-K
#define NJG  (24*SPG) // 144
#define VT_  250      // vocab tiles of 128
#define KT_  64       // logits K tiles of 16

// gate weight fragment offsets (uint4 units): [jt*8+mt][ktile][lane]
#define OFF_WIH0 0            // KT=32: 24*8*32*32 = 196608
#define OFF_WHH0 196608       // KT=64: 393216
#define OFF_WIH1 589824
#define OFF_WHH1 983040
#define GWF_TOT  1376256

// ---------------- persistent device state ----------------
__device__ float g_h0T[2][H_*B_];            // fp32 hidden, transposed [k][b], ping-pong
__device__ float g_h1T[2][H_*B_];
__device__ float g_giP0[SPG][G3_*B_];        // split-K partials, layout [j][b]
__device__ float g_ghP0[SPG][G3_*B_];
__device__ float g_giP1[SPG][G3_*B_];
__device__ float g_ghP1[SPG][G3_*B_];
__device__ unsigned long long g_argmax[B_];  // packed (orderable_val<<32 | ~index)

// logits w_out bf16 hi/lo A-fragments: ((vt*8+mt)*KT_+kt)*32+lane -> uint4
__device__ uint4 g_wfHi[(size_t)VT_*8*KT_*32];
__device__ uint4 g_wfLo[(size_t)VT_*8*KT_*32];
// gate weight A-fragments
__device__ uint4 g_gwfHi[GWF_TOT];
__device__ uint4 g_gwfLo[GWF_TOT];
// B-fragments (activations) hi/lo: 1/2=h0 parity0/1, 3/4=h1 parity0/1
__device__ uint2 g_bfHi[5][64*4*32];
__device__ uint2 g_bfLo[5][64*4*32];

__device__ __forceinline__ float* hbuf(int code){
    switch(code){
        case 0:  return g_h0T[0];
        case 1:  return g_h0T[1];
        case 2:  return g_h1T[0];
        default: return g_h1T[1];
    }
}

__device__ __forceinline__ unsigned long long packv(float f, unsigned v){
    unsigned u = __float_as_uint(f);
    u = (u & 0x80000000u) ? ~u : (u | 0x80000000u);   // monotonic order-preserving map
    return ((unsigned long long)u << 32) | (unsigned long long)(0xFFFFFFFFu - v);
}

// baseline-sm_103 HMMA: m16n8k16 bf16 -> f32, accumulate in place
__device__ __forceinline__ void mma16816(float* d, const uint32_t* a, const uint32_t* b){
    asm volatile("mma.sync.aligned.m16n8k16.row.col.f32.bf16.bf16.f32 "
        "{%0,%1,%2,%3}, {%4,%5,%6,%7}, {%8,%9}, {%0,%1,%2,%3};"
        : "+f"(d[0]), "+f"(d[1]), "+f"(d[2]), "+f"(d[3])
        : "r"(a[0]), "r"(a[1]), "r"(a[2]), "r"(a[3]), "r"(b[0]), "r"(b[1]));
}

__device__ __forceinline__ void write_bfrag(int code, int k, int b, float hv){
    __nv_bfloat16 hi = __float2bfloat16(hv);
    __nv_bfloat16 lo = __float2bfloat16(hv - __bfloat162float(hi));
    int ktile = k >> 4, kin = k & 15;
    int reg = kin >> 3, c = kin & 7;
    int lane = (b & 7)*4 + (c >> 1);
    int ntile = b >> 3;
    int half = c & 1;
    size_t off = ((size_t)(ktile*4 + ntile)*32 + lane)*4 + reg*2 + half; // ushort units
    ((unsigned short*)g_bfHi[code])[off] = __bfloat16_as_ushort(hi);
    ((unsigned short*)g_bfLo[code])[off] = __bfloat16_as_ushort(lo);
}

// pack two floats to bf16x2 hi and lo words
__device__ __forceinline__ void split2(float x0, float x1, uint32_t& hw, uint32_t& lw){
    __nv_bfloat16 h0 = __float2bfloat16(x0), h1 = __float2bfloat16(x1);
    __nv_bfloat16 l0 = __float2bfloat16(x0 - __bfloat162float(h0));
    __nv_bfloat16 l1 = __float2bfloat16(x1 - __bfloat162float(h1));
    hw = (uint32_t)__bfloat16_as_ushort(h0) | ((uint32_t)__bfloat16_as_ushort(h1) << 16);
    lw = (uint32_t)__bfloat16_as_ushort(l0) | ((uint32_t)__bfloat16_as_ushort(l1) << 16);
}

// ---- shared gh GEMM body: ghP = h_old @ whh^T for one (layer, s, jt) ----
__device__ __forceinline__ void gh_body(int is_l1, int s, int jt, int p,
                                        int wid, int lane){
    const int KT = 64;
    const int matOff = is_l1 ? OFF_WHH1 : OFF_WHH0;
    const int bcode  = is_l1 ? (3+p) : (1+p);
    const uint2* __restrict__ bHi = g_bfHi[bcode];
    const uint2* __restrict__ bLo = g_bfLo[bcode];
    float* __restrict__ out = is_l1 ? g_ghP1[s] : g_ghP0[s];

    const int kt0 = (KT * s) / SPG;
    const int kt1 = (KT * (s+1)) / SPG;

    const uint4* __restrict__ aHi = g_gwfHi + matOff + ((size_t)(jt*8 + wid)*KT)*32 + lane;
    const uint4* __restrict__ aLo = g_gwfLo + matOff + ((size_t)(jt*8 + wid)*KT)*32 + lane;

    float acc[4][4];
    #pragma unroll
    for (int n=0;n<4;n++){ acc[n][0]=0.f; acc[n][1]=0.f; acc[n][2]=0.f; acc[n][3]=0.f; }

    uint4 ah = aHi[(size_t)kt0*32], al = aLo[(size_t)kt0*32];
    for (int kt = kt0; kt < kt1; kt++){
        uint4 ah_n, al_n;
        if (kt+1 < kt1){ ah_n = aHi[(size_t)(kt+1)*32]; al_n = aLo[(size_t)(kt+1)*32]; }
        uint2 bh[4], bl[4];
        #pragma unroll
        for (int nt=0; nt<4; nt++){
            bh[nt] = bHi[(kt*4 + nt)*32 + lane];
            bl[nt] = bLo[(kt*4 + nt)*32 + lane];
        }
        #pragma unroll
        for (int nt=0; nt<4; nt++){
            mma16816(acc[nt], (const uint32_t*)&ah, (const uint32_t*)&bh[nt]);
            mma16816(acc[nt], (const uint32_t*)&ah, (const uint32_t*)&bl[nt]);
            mma16816(acc[nt], (const uint32_t*)&al, (const uint32_t*)&bh[nt]);
        }
        ah = ah_n; al = al_n;
    }

    const int g  = lane >> 2, c0 = (lane & 3)*2;
    const int j0 = jt*128 + wid*16 + g;
    #pragma unroll
    for (int nt=0; nt<4; nt++){
        const int b = nt*8 + c0;
        out[(size_t)j0     *B_ + b    ] = acc[nt][0];
        out[(size_t)j0     *B_ + b + 1] = acc[nt][1];
        out[(size_t)(j0+8) *B_ + b    ] = acc[nt][2];
        out[(size_t)(j0+8) *B_ + b + 1] = acc[nt][3];
    }
}

// =============================================================================
// Standalone gh kernel (pre-loop seed only): grid = 2*NJG = 288
// =============================================================================
__global__ __launch_bounds__(256) void k_gh(int p){
    const int tid = threadIdx.x, wid = tid >> 5, lane = tid & 31;
    const int is_l1 = (blockIdx.x >= NJG);
    const int rem = is_l1 ? blockIdx.x - NJG : blockIdx.x;
    gh_body(is_l1, rem/24, rem%24, p, wid, lane);
}

// =============================================================================
// Layer-0 input gates with fused embedding gather: giP0 = emb[tok] @ wih0^T
// grid = NJG; tok = argmax(t-1) (SOS at t=0); direct float2 loads from emb.
// =============================================================================
__global__ __launch_bounds__(256) void k_gates_gi0(const float* __restrict__ emb, int t)
{
    __shared__ int tok_s[B_];
    const int tid = threadIdx.x, wid = tid >> 5, lane = tid & 31;
    const int s = blockIdx.x / 24, jt = blockIdx.x % 24;
    const int KT = 32;   // E=512

    if (tid < B_){
        int tk = SOS_;
        if (t > 0) tk = (int)(0xFFFFFFFFu - (unsigned)(g_argmax[tid] & 0xFFFFFFFFull));
        tok_s[tid] = tk;
    }
    __syncthreads();

    const int kt0 = (KT * s) / SPG;
    const int kt1 = (KT * (s+1)) / SPG;

    const uint4* __restrict__ aHi = g_gwfHi + OFF_WIH0 + ((size_t)(jt*8 + wid)*KT)*32 + lane;
    const uint4* __restrict__ aLo = g_gwfLo + OFF_WIH0 + ((size_t)(jt*8 + wid)*KT)*32 + lane;

    const int n_in = lane >> 2;
    const int kc   = (lane & 3)*2;
    const float* __restrict__ row[4];
    #pragma unroll
    for (int nt=0; nt<4; nt++) row[nt] = emb + (size_t)tok_s[nt*8 + n_in]*E_;

    float acc[4][4];
    #pragma unroll
    for (int n=0;n<4;n++){ acc[n][0]=0.f; acc[n][1]=0.f; acc[n][2]=0.f; acc[n][3]=0.f; }

    uint4 ah = aHi[(size_t)kt0*32], al = aLo[(size_t)kt0*32];
    for (int kt = kt0; kt < kt1; kt++){
        uint4 ah_n, al_n;
        if (kt+1 < kt1){ ah_n = aHi[(size_t)(kt+1)*32]; al_n = aLo[(size_t)(kt+1)*32]; }
        const int k0 = kt*16 + kc;
        #pragma unroll
        for (int nt=0; nt<4; nt++){
            float2 x0 = *(const float2*)(row[nt] + k0);
            float2 x1 = *(const float2*)(row[nt] + k0 + 8);
            uint2 bh, bl;
            split2(x0.x, x0.y, bh.x, bl.x);
            split2(x1.x, x1.y, bh.y, bl.y);
            mma16816(acc[nt], (const uint32_t*)&ah, (const uint32_t*)&bh);
            mma16816(acc[nt], (const uint32_t*)&ah, (const uint32_t*)&bl);
            mma16816(acc[nt], (const uint32_t*)&al, (const uint32_t*)&bh);
        }
        ah = ah_n; al = al_n;
    }

    const int g  = lane >> 2, c0 = (lane & 3)*2;
    const int j0 = jt*128 + wid*16 + g;
    float* __restrict__ out = g_giP0[s];
    #pragma unroll
    for (int nt=0; nt<4; nt++){
        const int b = nt*8 + c0;
        out[(size_t)j0     *B_ + b    ] = acc[nt][0];
        out[(size_t)j0     *B_ + b + 1] = acc[nt][1];
        out[(size_t)(j0+8) *B_ + b    ] = acc[nt][2];
        out[(size_t)(j0+8) *B_ + b + 1] = acc[nt][3];
    }
}

// =============================================================================
// Layer-1 input gates: giP1 = h0_new @ wih1^T.  grid = NJG.
// =============================================================================
__global__ __launch_bounds__(256) void k_gates_gi1(int bcode)
{
    const int tid = threadIdx.x, wid = tid >> 5, lane = tid & 31;
    const int s = blockIdx.x / 24, jt = blockIdx.x % 24;
    const int KT = 64;

    const uint2* __restrict__ bHi = g_bfHi[bcode];
    const uint2* __restrict__ bLo = g_bfLo[bcode];
    const int kt0 = (KT * s) / SPG;
    const int kt1 = (KT * (s+1)) / SPG;

    const uint4* __restrict__ aHi = g_gwfHi + OFF_WIH1 + ((size_t)(jt*8 + wid)*KT)*32 + lane;
    const uint4* __restrict__ aLo = g_gwfLo + OFF_WIH1 + ((size_t)(jt*8 + wid)*KT)*32 + lane;

    float acc[4][4];
    #pragma unroll
    for (int n=0;n<4;n++){ acc[n][0]=0.f; acc[n][1]=0.f; acc[n][2]=0.f; acc[n][3]=0.f; }

    uint4 ah = aHi[(size_t)kt0*32], al = aLo[(size_t)kt0*32];
    for (int kt = kt0; kt < kt1; kt++){
        uint4 ah_n, al_n;
        if (kt+1 < kt1){ ah_n = aHi[(size_t)(kt+1)*32]; al_n = aLo[(size_t)(kt+1)*32]; }
        uint2 bh[4], bl[4];
        #pragma unroll
        for (int nt=0; nt<4; nt++){
            bh[nt] = bHi[(kt*4 + nt)*32 + lane];
            bl[nt] = bLo[(kt*4 + nt)*32 + lane];
        }
        #pragma unroll
        for (int nt=0; nt<4; nt++){
            mma16816(acc[nt], (const uint32_t*)&ah, (const uint32_t*)&bh[nt]);
            mma16816(acc[nt], (const uint32_t*)&ah, (const uint32_t*)&bl[nt]);
            mma16816(acc[nt], (const uint32_t*)&al, (const uint32_t*)&bh[nt]);
        }
        ah = ah_n; al = al_n;
    }

    const int g  = lane >> 2, c0 = (lane & 3)*2;
    const int j0 = jt*128 + wid*16 + g;
    float* __restrict__ out = g_giP1[s];
    #pragma unroll
    for (int nt=0; nt<4; nt++){
        const int b = nt*8 + c0;
        out[(size_t)j0     *B_ + b    ] = acc[nt][0];
        out[(size_t)j0     *B_ + b + 1] = acc[nt][1];
        out[(size_t)(j0+8) *B_ + b    ] = acc[nt][2];
        out[(size_t)(j0+8) *B_ + b + 1] = acc[nt][3];
    }
}

// =============================================================================
// GRU combine: sums split-K partials, writes fp32 h + bf16 hi/lo B-fragments
// =============================================================================
__global__ __launch_bounds__(256) void k_combine(
    const float* __restrict__ bih, const float* __restrict__ bhh,
    int code_old, int code_new, int fragcode, int reset, int layer)
{
    int idx = blockIdx.x*256 + threadIdx.x;   // 0..32767
    int b = idx & 31, k = idx >> 5;
    const float* giP = layer ? (const float*)g_giP1 : (const float*)g_giP0;
    const float* ghP = layer ? (const float*)g_ghP1 : (const float*)g_ghP0;
    float gr=0.f, gz=0.f, gn=0.f, hr=0.f, hz=0.f, hn=0.f;
    #pragma unroll
    for (int s=0;s<SPG;s++){
        const float* gi = giP + (size_t)s*G3_*B_;
        const float* gh = ghP + (size_t)s*G3_*B_;
        gr += gi[(size_t)k*B_ + b];
        gz += gi[(size_t)(H_  +k)*B_ + b];
        gn += gi[(size_t)(2*H_+k)*B_ + b];
        hr += gh[(size_t)k*B_ + b];
        hz += gh[(size_t)(H_  +k)*B_ + b];
        hn += gh[(size_t)(2*H_+k)*B_ + b];
    }
    float r = 1.f/(1.f + expf(-(gr + bih[k]     + hr + bhh[k])));
    float z = 1.f/(1.f + expf(-(gz + bih[H_+k]  + hz + bhh[H_+k])));
    float n = tanhf(gn + bih[2*H_+k] + r*(hn + bhh[2*H_+k]));
    float h = hbuf(code_old)[(size_t)k*B_ + b];
    float hv = (1.f - z)*n + z*h;
    hbuf(code_new)[(size_t)k*B_ + b] = hv;
    write_bfrag(fragcode, k, b, hv);
    if (reset && idx < B_) g_argmax[idx] = 0ULL;
}

// =============================================================================
// w_out -> bf16 hi/lo per-lane A-fragments (once per replay)
// =============================================================================
__global__ __launch_bounds__(256) void k_wsplit(const float* __restrict__ w){
    size_t gid = (size_t)blockIdx.x*256 + threadIdx.x;  // 4,096,000
    int lane  = (int)(gid & 31);
    int ktile = (int)((gid >> 5) & 63);
    int mtile = (int)((gid >> 11) & 7);
    int vt    = (int)(gid >> 14);
    int g  = lane >> 2, c0 = (lane & 3)*2;
    int v0 = vt*128 + mtile*16;
    int k0 = ktile*16;
    uint32_t hi[4], lo[4];
    #pragma unroll
    for (int r=0;r<4;r++){
        int row = v0 + g + (r & 1)*8;
        int col = k0 + c0 + (r >> 1)*8;
        split2(w[(size_t)row*H_ + col], w[(size_t)row*H_ + col + 1], hi[r], lo[r]);
    }
    g_wfHi[gid] = make_uint4(hi[0], hi[1], hi[2], hi[3]);
    g_wfLo[gid] = make_uint4(lo[0], lo[1], lo[2], lo[3]);
}

// gate weight W[G3_][K] -> A-fragments at offset matOff (once per replay)
__global__ __launch_bounds__(256) void k_wsplit_g(const float* __restrict__ w, int K, int matOff){
    size_t gid = (size_t)blockIdx.x*256 + threadIdx.x;
    const int KT = K >> 4;
    int lane  = (int)(gid & 31);
    int ktile = (int)((gid >> 5) % KT);
    int mt    = (int)((gid >> 5) / KT);
    int g  = lane >> 2, c0 = (lane & 3)*2;
    int j0 = mt*16;
    int k0 = ktile*16;
    uint32_t hi[4], lo[4];
    #pragma unroll
    for (int r=0;r<4;r++){
        int row = j0 + g + (r & 1)*8;
        int col = k0 + c0 + (r >> 1)*8;
        split2(w[(size_t)row*K + col], w[(size_t)row*K + col + 1], hi[r], lo[r]);
    }
    g_gwfHi[matOff + gid] = make_uint4(hi[0], hi[1], hi[2], hi[3]);
    g_gwfLo[matOff + gid] = make_uint4(lo[0], lo[1], lo[2], lo[3]);
}

// =============================================================================
// Fused tail kernel: blocks [0,VT_) = logits(t) + fused argmax;
// blocks [VT_, VT_+2*NJG) = recurrent gates gh0/gh1 for step t+1.
// =============================================================================
__global__ __launch_bounds__(256,3) void k_fused(
    const float* __restrict__ bout, float* __restrict__ out, int t,
    int bcode_logits, int p_next)
{
    const int tid = threadIdx.x, wid = tid >> 5, lane = tid & 31;
    const int bid = blockIdx.x;

    if (bid >= VT_){
        // ---- recurrent gates for next step ----
        const int rem = bid - VT_;
        const int is_l1 = (rem >= NJG);
        const int r2 = is_l1 ? rem - NJG : rem;
        gh_body(is_l1, r2/24, r2%24, p_next, wid, lane);
        return;
    }

    // ---- logits tile ----
    __shared__ unsigned long long red[8][32];
    const int vt = bid;

    float acc[4][4];
    #pragma unroll
    for (int n=0;n<4;n++){ acc[n][0]=0.f; acc[n][1]=0.f; acc[n][2]=0.f; acc[n][3]=0.f; }

    const uint4* __restrict__ aHi = g_wfHi + ((size_t)(vt*8 + wid)*KT_)*32 + lane;
    const uint4* __restrict__ aLo = g_wfLo + ((size_t)(vt*8 + wid)*KT_)*32 + lane;
    const uint2* __restrict__ bHi = g_bfHi[bcode_logits];
    const uint2* __restrict__ bLo = g_bfLo[bcode_logits];

    uint4 ah = aHi[0], al = aLo[0];
    for (int kt = 0; kt < KT_; kt++){
        uint4 ah_n, al_n;
        if (kt < KT_-1){ ah_n = aHi[(kt+1)*32]; al_n = aLo[(kt+1)*32]; }
        uint2 bh[4], bl[4];
        #pragma unroll
        for (int nt=0; nt<4; nt++){
            bh[nt] = bHi[(kt*4 + nt)*32 + lane];
            bl[nt] = bLo[(kt*4 + nt)*32 + lane];
        }
        #pragma unroll
        for (int nt=0; nt<4; nt++){
            mma16816(acc[nt], (const uint32_t*)&ah, (const uint32_t*)&bh[nt]);
            mma16816(acc[nt], (const uint32_t*)&ah, (const uint32_t*)&bl[nt]);
            mma16816(acc[nt], (const uint32_t*)&al, (const uint32_t*)&bh[nt]);
        }
        ah = ah_n; al = al_n;
    }

    const int g  = lane >> 2, c0 = (lane & 3)*2;
    const int v0 = vt*128 + wid*16 + g;
    const float bias0 = bout[v0], bias1 = bout[v0 + 8];

    unsigned long long colmax[8];
    #pragma unroll
    for (int nt=0; nt<4; nt++){
        const int b = nt*8 + c0;
        float v00 = acc[nt][0] + bias0;
        float v01 = acc[nt][1] + bias0;
        float v10 = acc[nt][2] + bias1;
        float v11 = acc[nt][3] + bias1;
        out[((size_t)b    *T_ + t)*V_ + v0    ] = v00;
        out[((size_t)(b+1)*T_ + t)*V_ + v0    ] = v01;
        out[((size_t)b    *T_ + t)*V_ + v0 + 8] = v10;
        out[((size_t)(b+1)*T_ + t)*V_ + v0 + 8] = v11;
        unsigned long long p0 = packv(v00, (unsigned)v0);
        unsigned long long q0 = packv(v10, (unsigned)(v0+8));
        unsigned long long p1 = packv(v01, (unsigned)v0);
        unsigned long long q1 = packv(v11, (unsigned)(v0+8));
        colmax[nt*2]   = p0 > q0 ? p0 : q0;
        colmax[nt*2+1] = p1 > q1 ? p1 : q1;
    }
    #pragma unroll
    for (int q=0;q<8;q++){
        #pragma unroll
        for (int off=4; off<32; off<<=1){
            unsigned long long o = __shfl_xor_sync(0xFFFFFFFFu, colmax[q], off);
            if (o > colmax[q]) colmax[q] = o;
        }
    }
    if (lane < 4){
        #pragma unroll
        for (int nt=0; nt<4; nt++){
            red[wid][nt*8 + lane*2    ] = colmax[nt*2];
            red[wid][nt*8 + lane*2 + 1] = colmax[nt*2+1];
        }
    }
    __syncthreads();
    if (tid < B_){
        unsigned long long m = red[0][tid];
        #pragma unroll
        for (int w=1; w<8; w++) if (red[w][tid] > m) m = red[w][tid];
        atomicMax(&g_argmax[tid], m);
    }
}

// =============================================================================
// init / finalize / log_softmax
// =============================================================================
__global__ void k_init(const float* __restrict__ eh){
    int idx = blockIdx.x*256 + threadIdx.x;           // 0..65535
    int k = idx & (H_-1), b = (idx >> 10) & 31, l = idx >> 15;
    float v = eh[idx];
    (l ? g_h1T[0] : g_h0T[0])[(size_t)k*B_ + b] = v;
    write_bfrag(l ? 3 : 1, k, b, v);                  // parity-0 fragment buffers
}

__global__ void k_final(float* __restrict__ dst){
    int idx = blockIdx.x*256 + threadIdx.x;
    int k = idx & (H_-1), b = (idx >> 10) & 31, l = idx >> 15;
    dst[idx] = (l ? g_h1T[0] : g_h0T[0])[(size_t)k*B_ + b];   // parity 0 after 64 steps
}

__global__ __launch_bounds__(256) void k_lsm(float* __restrict__ out){
    float* p = out + (size_t)blockIdx.x * V_;
    __shared__ float red[256];
    float m = -3.4e38f;
    for (int i = threadIdx.x; i < V_; i += 256) m = fmaxf(m, p[i]);
    red[threadIdx.x] = m; __syncthreads();
    for (int s=128; s; s>>=1){
        if (threadIdx.x < s) red[threadIdx.x] = fmaxf(red[threadIdx.x], red[threadIdx.x+s]);
        __syncthreads();
    }
    m = red[0]; __syncthreads();
    float sum = 0.f;
    for (int i = threadIdx.x; i < V_; i += 256) sum += __expf(p[i] - m);
    red[threadIdx.x] = sum; __syncthreads();
    for (int s=128; s; s>>=1){
        if (threadIdx.x < s) red[threadIdx.x] += red[threadIdx.x+s];
        __syncthreads();
    }
    float lse = m + logf(red[0]);
    for (int i = threadIdx.x; i < V_; i += 256) p[i] -= lse;
}

// =============================================================================
extern "C" void kernel_launch(void* const* d_in, const int* in_sizes, int n_in,
                              void* d_out, int out_size) {
    const float* eh   = (const float*)d_in[1];   // encoder_hidden [2,32,1024]
    const float* emb  = (const float*)d_in[2];   // embedding [V,E]
    const float* wih0 = (const float*)d_in[3];
    const float* whh0 = (const float*)d_in[4];
    const float* bih0 = (const float*)d_in[5];
    const float* bhh0 = (const float*)d_in[6];
    const float* wih1 = (const float*)d_in[7];
    const float* whh1 = (const float*)d_in[8];
    const float* bih1 = (const float*)d_in[9];
    const float* bhh1 = (const float*)d_in[10];
    const float* wout = (const float*)d_in[11];
    const float* bout = (const float*)d_in[12];

    float* out  = (float*)d_out;                 // [B,T,V] log-softmax
    float* hfin = out + (size_t)B_*T_*V_;        // [2,B,H]

    // per-replay weight prep (amortized over 64 steps)
    k_wsplit<<<(VT_*8*KT_*32)/256, 256>>>(wout);
    k_wsplit_g<<<(24*8*(E_/16)*32)/256, 256>>>(wih0, E_, OFF_WIH0);
    k_wsplit_g<<<(24*8*(H_/16)*32)/256, 256>>>(whh0, H_, OFF_WHH0);
    k_wsplit_g<<<(24*8*(H_/16)*32)/256, 256>>>(wih1, H_, OFF_WIH1);
    k_wsplit_g<<<(24*8*(H_/16)*32)/256, 256>>>(whh1, H_, OFF_WHH1);

    k_init<<<256,256>>>(eh);
    k_gh<<<2*NJG, 256>>>(0);   // seed gh for t=0 from init state (p=0)

    for (int t=0; t<T_; t++){
        const int p = t & 1;
        // gi0: emb gather from argmax(t-1)
        k_gates_gi0<<<NJG, 256>>>(emb, t);
        // combine layer 0 (ghP0 from previous fused/seed launch)
        k_combine<<<H_*B_/256,256>>>(bih0, bhh0, p, 1-p, 1+(1-p), 0, 0);
        // gi1 from h0_new fragments
        k_gates_gi1<<<NJG, 256>>>(1+(1-p));
        // combine layer 1 (+ argmax reset, before logits accumulates)
        k_combine<<<H_*B_/256,256>>>(bih1, bhh1, 2+p, 3-p, 3+(1-p), 1, 1);
        // fused: logits(t) from h1_new + recurrent gates for step t+1
        k_fused<<<VT_ + 2*NJG, 256>>>(bout, out, t, 3+(1-p), 1-p);
    }
    k_final<<<256,256>>>(hfin);
    k_lsm<<<B_*T_,256>>>(out);
}